// round 15
// baseline (speedup 1.0000x reference)
#include <cuda_runtime.h>
#include <cuda_fp16.h>
#include <cstdint>
#include <math.h>

// ---------------- problem constants ----------------
#define NUM_E 1024
#define DIM   64
#define TT    2048
#define BB    32
#define NROWS (BB * TT)          // 65536
#define NELEM (BB * DIM * TT)    // 4194304

// output layout (flattened tuple, fp32)
#define COMMIT_OFF 4194304
#define PERP_OFF   4194305
#define AVG_OFF    4194306
#define IDX_OFF    4195330
#define USAGE_OFF  4260866

// ---------------- tiling ----------------
#define ROWS_CTA 64                  // rows per tile (4 m-tiles)
#define NTILES   (NROWS / ROWS_CTA)  // 1024
#define NCH      8                   // code chunks of 128
#define CHB      32768               // full 2-split packed chunk (8 pkt)
#define CHB2     16384               // split0 half (4 pkt)
#define INV2048  4.8828125e-4f

// ---- main kernel smem ----
#define SA_OFF   0                   // A frags split0: 8KB
#define SB_OFF   8192                // B split0 frags: 128KB
#define SE2_OFF  139264              // 4KB
#define SXN_OFF  143360
#define SRN_OFF  143616
#define SB1_OFF  143872
#define SI1_OFF  145920
#define SB2_OFF  147968
#define SWIN_OFF 150016              // 64*4 winner idx (-1 = flagged)
#define SX_OFF   150528              // x fp32 tile: 64*64*4 = 16KB
#define SMEM_MAIN 166912

// ---- pass2 kernel smem (R12-proven) ----
#define P2_SA    0                   // A frags 2-split: 16KB
#define P2_SB    16384               // 2 * 32KB
#define P2_SE2   81920               // 4KB
#define P2_SRF   86016               // 64*8*4
#define P2_SRI   88064               // 64*8*4
#define P2_SL    90112               // 64*4
#define SMEM_P2  90368

// ---------------- device scratch ----------------
__device__ __align__(16) unsigned char g_Bp[NCH * CHB];  // 2-split packed B
__device__ float g_e2[NUM_E];
__device__ float g_hm2[32];
__device__ float g_e0m2[32];
__device__ unsigned long long g_slot[NROWS];   // packed (okey(score)<<10|idx); init by main for flagged rows
__device__ int   g_list[NROWS];
__device__ int   g_cnt;
__device__ int   g_gdone;
__device__ int   g_counts[NUM_E];
__device__ float g_sumsq;

// ---------------- helpers ----------------
__device__ __forceinline__ uint32_t smem_u32(const void* p) {
    uint32_t a;
    asm("{ .reg .u64 t; cvta.to.shared.u64 t, %1; cvt.u32.u64 %0, t; }" : "=r"(a) : "l"(p));
    return a;
}
__device__ __forceinline__ void cp16(uint32_t saddr, const void* g) {
    asm volatile("cp.async.cg.shared.global [%0], [%1], 16;" :: "r"(saddr), "l"(g));
}
__device__ __forceinline__ void cp_commit() {
    asm volatile("cp.async.commit_group;" ::: "memory");
}
__device__ __forceinline__ void mma16816(float* d, const uint4 a, const uint2 b) {
    asm volatile(
        "mma.sync.aligned.m16n8k16.row.col.f32.f16.f16.f32 "
        "{%0,%1,%2,%3}, {%4,%5,%6,%7}, {%8,%9}, {%0,%1,%2,%3};"
        : "+f"(d[0]), "+f"(d[1]), "+f"(d[2]), "+f"(d[3])
        : "r"(a.x), "r"(a.y), "r"(a.z), "r"(a.w), "r"(b.x), "r"(b.y));
}
__device__ __forceinline__ void split2(float v, uint32_t& u0, uint32_t& u1) {
    __half h0 = __float2half_rn(v);
    float f0 = __half2float(h0);
    __half h1 = __float2half_rn((v - f0) * 2048.0f);
    u0 = (uint32_t)__half_as_ushort(h0);
    u1 = (uint32_t)__half_as_ushort(h1);
}
__device__ __forceinline__ uint32_t okey(float f) {
    uint32_t b = __float_as_uint(f);
    return (b & 0x80000000u) ? ~b : (b | 0x80000000u);
}

// ---------------- prep: 4 threads/code (32 blocks x 128 thr) ----------------
__global__ void prep_kernel(const float* __restrict__ embed) {
    __shared__ float smx1[4], smx2[4];
    const int tid = threadIdx.x, lane = tid & 31, w = tid >> 5;
    const int c = blockIdx.x * 32 + (tid >> 2);
    const int q = tid & 3;

    const float* e = embed + (size_t)c * DIM + q * 16;
    uint32_t h0[8], h1[8];
    float e2 = 0.f, e02 = 0.f, res2 = 0.f;
#pragma unroll
    for (int j = 0; j < 8; ++j) {
        float2 v = *(const float2*)(e + 2 * j);
        e2 += v.x * v.x + v.y * v.y;
        uint32_t a0, a1, b0, b1;
        split2(v.x, a0, a1);
        split2(v.y, b0, b1);
        float fa = __half2float(__ushort_as_half((unsigned short)a0));
        float fb = __half2float(__ushort_as_half((unsigned short)b0));
        e02 += fa * fa + fb * fb;
        float rx = v.x - fa, ry = v.y - fb;
        res2 += rx * rx + ry * ry;
        h0[j] = a0 | (b0 << 16);
        h1[j] = a1 | (b1 << 16);
    }
    e2 += __shfl_xor_sync(0xffffffffu, e2, 1);
    e2 += __shfl_xor_sync(0xffffffffu, e2, 2);
    if (q == 0) {
        g_e2[c] = e2;
        g_counts[c] = 0;
        if (c == 0) { g_sumsq = 0.f; g_cnt = 0; g_gdone = 0; }
    }

    const int chunk = c >> 7, n_in = c & 127, nt = n_in >> 3, lq = n_in & 7;
    uint32_t* dstb = (uint32_t*)(g_Bp + (size_t)chunk * CHB);
#pragma unroll
    for (int sp = 0; sp < 2; ++sp) {
        const int pkt = sp * 4 + q;
        const uint32_t* hp = sp ? h1 : h0;
#pragma unroll
        for (int cc = 0; cc < 4; ++cc) {
            uint32_t* d = dstb + (((pkt * 16 + nt) * 32) + 4 * lq + cc) * 2;
            d[0] = hp[cc];
            d[1] = hp[4 + cc];
        }
    }
#pragma unroll
    for (int o = 16; o; o >>= 1) {
        res2 = fmaxf(res2, __shfl_xor_sync(0xffffffffu, res2, o));
        e02  = fmaxf(e02,  __shfl_xor_sync(0xffffffffu, e02,  o));
    }
    if (lane == 0) { smx1[w] = res2; smx2[w] = e02; }
    __syncthreads();
    if (tid == 0) {
        g_hm2[blockIdx.x]  = fmaxf(fmaxf(smx1[0], smx1[1]), fmaxf(smx1[2], smx1[3]));
        g_e0m2[blockIdx.x] = fmaxf(fmaxf(smx2[0], smx2[1]), fmaxf(smx2[2], smx2[3]));
    }
}

// ---------------- main: persistent 1-product HMMA + top-2 + flag + fused unflagged gather ----------------
__global__ void __launch_bounds__(512, 1)
vq_mma_kernel(const float* __restrict__ x, const float* __restrict__ embed,
              float* __restrict__ out) {
    extern __shared__ char sm[];
    uint32_t* sA   = (uint32_t*)(sm + SA_OFF);
    float*    sE2  = (float*)(sm + SE2_OFF);
    float*    sXn  = (float*)(sm + SXN_OFF);
    float*    sRn  = (float*)(sm + SRN_OFF);
    float*    sB1  = (float*)(sm + SB1_OFF);
    int*      sI1  = (int*)(sm + SI1_OFF);
    float*    sB2  = (float*)(sm + SB2_OFF);
    int*      sWin = (int*)(sm + SWIN_OFF);
    float*    sX   = (float*)(sm + SX_OFF);
    const uint32_t sBaddr = smem_u32(sm + SB_OFF);

    const int tid = threadIdx.x, lane = tid & 31, w = tid >> 5;
    const int rg = w >> 3, cg = w & 7;

    // load split0 halves of all 8 chunks (128KB) ONCE
    for (int k = tid; k < 8192; k += 512) {
        const int chk = k >> 10, off = k & 1023;
        cp16(sBaddr + k * 16, (const char*)g_Bp + (size_t)chk * CHB + off * 16);
    }
    cp_commit();
    for (int i = tid; i < NUM_E; i += 512) sE2[i] = g_e2[i];

    float hm2 = g_hm2[0], e0m2 = g_e0m2[0];
#pragma unroll
    for (int i = 1; i < 32; ++i) {
        hm2 = fmaxf(hm2, g_hm2[i]);
        e0m2 = fmaxf(e0m2, g_e0m2[i]);
    }
    const float HM = sqrtf(hm2), E0M = sqrtf(e0m2);

    const int r = tid >> 3, o = tid & 7;
    const int q = o >> 1, halfq = o & 1;
    const int mt = r >> 4, rr = r & 15;
    const int wsel = ((rr < 8) ? 0 : 1) + (halfq ? 2 : 0);

    // gather-phase roles
    const int gr = tid & 63, go = tid >> 6;   // 64 rows x 8 octants

    float xv[8];
    {
        const int grow = blockIdx.x * ROWS_CTA + r;
        const float* xp = x + (size_t)(grow >> 11) * (DIM * TT) + (grow & (TT - 1));
#pragma unroll
        for (int j = 0; j < 8; ++j) xv[j] = xp[(size_t)(8 * o + j) * TT];
    }
    asm volatile("cp.async.wait_group 0;" ::: "memory");
    __syncthreads();

    float my_sumsq = 0.f;

    for (int tile = blockIdx.x; tile < NTILES; tile += gridDim.x) {
        {
            uint32_t h0[4];
            float x2 = 0.f, xi2 = 0.f;
#pragma unroll
            for (int j = 0; j < 4; ++j) {
                float va = xv[2 * j], vb = xv[2 * j + 1];
                sX[r * 64 + 8 * o + 2 * j]     = va;
                sX[r * 64 + 8 * o + 2 * j + 1] = vb;
                __half ha = __float2half_rn(va), hb = __float2half_rn(vb);
                float fa = __half2float(ha), fb = __half2float(hb);
                float ra = va - fa, rb = vb - fb;
                x2 += va * va + vb * vb;
                xi2 += ra * ra + rb * rb;
                h0[j] = (uint32_t)__half_as_ushort(ha) | ((uint32_t)__half_as_ushort(hb) << 16);
            }
#pragma unroll
            for (int off = 1; off < 8; off <<= 1) {
                x2  += __shfl_xor_sync(0xffffffffu, x2,  off);
                xi2 += __shfl_xor_sync(0xffffffffu, xi2, off);
            }
            if (o == 0) { sXn[r] = sqrtf(x2); sRn[r] = sqrtf(xi2); }
#pragma unroll
            for (int cc = 0; cc < 4; ++cc)
                sA[(((mt * 4 + q) * 32) + 4 * (rr & 7) + cc) * 4 + wsel] = h0[cc];
        }
        __syncthreads();

        float xn[8];
        {
            const int ntile = tile + gridDim.x;
            if (ntile < NTILES) {
                const int grow = ntile * ROWS_CTA + r;
                const float* xp = x + (size_t)(grow >> 11) * (DIM * TT) + (grow & (TT - 1));
#pragma unroll
                for (int j = 0; j < 8; ++j) xn[j] = xp[(size_t)(8 * o + j) * TT];
            } else {
#pragma unroll
                for (int j = 0; j < 8; ++j) xn[j] = 0.f;
            }
        }

        float b1_[4] = {3.4e38f, 3.4e38f, 3.4e38f, 3.4e38f};
        float b2_[4] = {3.4e38f, 3.4e38f, 3.4e38f, 3.4e38f};
        int   i1_[4] = {0, 0, 0, 0};

#define UPD(h, s, c) do { \
        if ((s) < b1_[h]) { b2_[h] = b1_[h]; b1_[h] = (s); i1_[h] = (c); } \
        else if ((s) < b2_[h]) b2_[h] = (s); \
    } while (0)

        for (int ch = 0; ch < NCH; ++ch) {
            const uint32_t* Bb = (const uint32_t*)(sm + SB_OFF + ch * CHB2);
            float acc[2][2][4];
#pragma unroll
            for (int m = 0; m < 2; ++m)
#pragma unroll
                for (int n = 0; n < 2; ++n)
#pragma unroll
                    for (int j = 0; j < 4; ++j) acc[m][n][j] = 0.f;
#pragma unroll
            for (int kt = 0; kt < 4; ++kt) {
                uint4 Af[2];
#pragma unroll
                for (int m = 0; m < 2; ++m)
                    Af[m] = *(const uint4*)(sA + ((((rg * 2 + m) * 4 + kt) * 32) + lane) * 4);
#pragma unroll
                for (int n = 0; n < 2; ++n) {
                    uint2 Bf = *(const uint2*)(Bb + (((kt * 16 + cg * 2 + n) * 32) + lane) * 2);
#pragma unroll
                    for (int m = 0; m < 2; ++m) mma16816(acc[m][n], Af[m], Bf);
                }
            }
            const int cb = ch * 128 + cg * 16 + 2 * (lane & 3);
#pragma unroll
            for (int n = 0; n < 2; ++n) {
                const int c0 = cb + n * 8;
                const float ea = sE2[c0], eb = sE2[c0 + 1];
#pragma unroll
                for (int m = 0; m < 2; ++m) {
                    const int ha = 2 * m, hb = 2 * m + 1;
                    float s0 = fmaf(-2.f, acc[m][n][0], ea);
                    float s1 = fmaf(-2.f, acc[m][n][1], eb);
                    float s2 = fmaf(-2.f, acc[m][n][2], ea);
                    float s3 = fmaf(-2.f, acc[m][n][3], eb);
                    UPD(ha, s0, c0); UPD(ha, s1, c0 + 1);
                    UPD(hb, s2, c0); UPD(hb, s3, c0 + 1);
                }
            }
        }
#undef UPD

#pragma unroll
        for (int h = 0; h < 4; ++h) {
#pragma unroll
            for (int off = 1; off < 4; off <<= 1) {
                float ob1 = __shfl_xor_sync(0xffffffffu, b1_[h], off);
                int   oi1 = __shfl_xor_sync(0xffffffffu, i1_[h], off);
                float ob2 = __shfl_xor_sync(0xffffffffu, b2_[h], off);
                if (ob1 < b1_[h] || (ob1 == b1_[h] && oi1 < i1_[h])) {
                    b2_[h] = fminf(b1_[h], ob2);
                    b1_[h] = ob1; i1_[h] = oi1;
                } else {
                    b2_[h] = fminf(b2_[h], ob1);
                }
            }
        }
        if ((lane & 3) == 0) {
            const int qq = lane >> 2;
#pragma unroll
            for (int h = 0; h < 4; ++h) {
                const int m = h >> 1, hb = h & 1;
                const int row = rg * 32 + m * 16 + hb * 8 + qq;
                sB1[row * 8 + cg] = b1_[h];
                sI1[row * 8 + cg] = i1_[h];
                sB2[row * 8 + cg] = b2_[h];
            }
        }
        __syncthreads();

        if (tid < ROWS_CTA) {
            float B1 = sB1[tid * 8], B2 = sB2[tid * 8];
            int   I1 = sI1[tid * 8];
#pragma unroll
            for (int g = 1; g < 8; ++g) {
                float ob1 = sB1[tid * 8 + g], ob2 = sB2[tid * 8 + g];
                int   oi1 = sI1[tid * 8 + g];
                if (ob1 < B1 || (ob1 == B1 && oi1 < I1)) {
                    B2 = fminf(B1, ob2);
                    B1 = ob1; I1 = oi1;
                } else {
                    B2 = fminf(B2, ob1);
                }
            }
            const float Wt = 4.0f * (sXn[tid] * HM + sRn[tid] * E0M) + 0.02f;
            const int grow = tile * ROWS_CTA + tid;
            if (B2 - B1 > Wt) {
                sWin[tid] = I1;
                out[IDX_OFF + grow] = (float)I1;
                atomicAdd(&g_counts[I1], 1);
            } else {
                sWin[tid] = -1;
                g_slot[grow] = 0xFFFFFFFFFFFFFFFFull;
                const int pos = atomicAdd(&g_cnt, 1);
                g_list[pos] = grow;
            }
        }
        __syncthreads();

        // ---- fused gather for unflagged rows of this tile ----
        {
            const int bi = sWin[gr];
            if (bi >= 0) {
                const int grow = tile * ROWS_CTA + gr;
                const int b_i = grow >> 11, t_i = grow & (TT - 1);
                const float4* ep = (const float4*)(embed + (size_t)bi * DIM + go * 8);
                const float* xs = sX + gr * 64 + go * 8;
                float* op = out + ((size_t)b_i * DIM + go * 8) * TT + t_i;
                float4 e0 = ep[0], e1 = ep[1];
                float ev[8] = {e0.x, e0.y, e0.z, e0.w, e1.x, e1.y, e1.z, e1.w};
#pragma unroll
                for (int j = 0; j < 8; ++j) {
                    float xvv = xs[j];
                    float d = ev[j] - xvv;
                    op[(size_t)j * TT] = xvv + d;
                    my_sumsq = fmaf(d, d, my_sumsq);
                }
            }
        }
        __syncthreads();   // protect sX/sWin/sA before next tile overwrites

#pragma unroll
        for (int j = 0; j < 8; ++j) xv[j] = xn[j];
    }

    // CTA-level commitment reduction, one atomic per CTA
    {
        __shared__ float wsum[16];
#pragma unroll
        for (int off = 16; off; off >>= 1)
            my_sumsq += __shfl_down_sync(0xffffffffu, my_sumsq, off);
        if (lane == 0) wsum[w] = my_sumsq;
        __syncthreads();
        if (w == 0) {
            float v = (lane < 16) ? wsum[lane] : 0.f;
#pragma unroll
            for (int off = 8; off; off >>= 1) v += __shfl_down_sync(0xffffffffu, v, off);
            if (lane == 0) atomicAdd(&g_sumsq, v);
        }
    }
}

// ---------------- pass2 (R12-proven): exact 2-split HMMA rescore, half-tiles ----------------
__global__ void __launch_bounds__(512, 2)
pass2_kernel(const float* __restrict__ x) {
    extern __shared__ char sm[];
    uint32_t* sA  = (uint32_t*)(sm + P2_SA);
    float*    sE2 = (float*)(sm + P2_SE2);
    float*    sRF = (float*)(sm + P2_SRF);
    int*      sRI = (int*)(sm + P2_SRI);
    int*      sL  = (int*)(sm + P2_SL);
    const uint32_t sBaddr = smem_u32(sm + P2_SB);

    const int tid = threadIdx.x, lane = tid & 31, w = tid >> 5;
    const int rg = w >> 3, cg = w & 7;
    const int cnt = g_cnt;

    for (int i = tid; i < NUM_E; i += 512) sE2[i] = g_e2[i];

    for (int ht = blockIdx.x; (ht >> 1) * 64 < cnt; ht += gridDim.x) {
        const int pair = ht >> 1, chalf = ht & 1;
        const int c0ch = chalf * 4;

        if (tid < ROWS_CTA) {
            const int p = pair * ROWS_CTA + tid;
            sL[tid] = (p < cnt) ? g_list[p] : -1;
        }
        __syncthreads();

        for (int k = tid; k < CHB / 16; k += 512)
            cp16(sBaddr + k * 16, (const char*)g_Bp + (size_t)c0ch * CHB + k * 16);
        cp_commit();
        for (int k = tid; k < CHB / 16; k += 512)
            cp16(sBaddr + CHB + k * 16, (const char*)g_Bp + (size_t)(c0ch + 1) * CHB + k * 16);
        cp_commit();

        {
            const int r = tid >> 3, o = tid & 7;
            const int q = o >> 1, halfq = o & 1;
            int grow = sL[r];
            if (grow < 0) grow = 0;
            const float* xp = x + (size_t)(grow >> 11) * (DIM * TT) + (grow & (TT - 1));
            uint32_t h0[4], h1[4];
#pragma unroll
            for (int j = 0; j < 4; ++j) {
                float va = xp[(size_t)(8 * o + 2 * j) * TT];
                float vb = xp[(size_t)(8 * o + 2 * j + 1) * TT];
                uint32_t a0, a1, b0, b1;
                split2(va, a0, a1);
                split2(vb, b0, b1);
                h0[j] = a0 | (b0 << 16);
                h1[j] = a1 | (b1 << 16);
            }
            const int mt = r >> 4, rr = r & 15;
            const int wsel = ((rr < 8) ? 0 : 1) + (halfq ? 2 : 0);
#pragma unroll
            for (int sp = 0; sp < 2; ++sp) {
                const int pkt = sp * 4 + q;
                const uint32_t* hp = sp ? h1 : h0;
#pragma unroll
                for (int cc = 0; cc < 4; ++cc)
                    sA[(((mt * 8 + pkt) * 32) + 4 * (rr & 7) + cc) * 4 + wsel] = hp[cc];
            }
        }
        __syncthreads();

        float best[4];
        int   bidx[4];
#pragma unroll
        for (int h = 0; h < 4; ++h) { best[h] = 3.4e38f; bidx[h] = 0; }

        for (int ch = 0; ch < 4; ++ch) {
            if (ch < 3) asm volatile("cp.async.wait_group 1;" ::: "memory");
            else        asm volatile("cp.async.wait_group 0;" ::: "memory");
            __syncthreads();
            const uint32_t* Bb = (const uint32_t*)(sm + P2_SB + (ch & 1) * CHB);

            float acc[2][2][4];
#pragma unroll
            for (int m = 0; m < 2; ++m)
#pragma unroll
                for (int n = 0; n < 2; ++n)
#pragma unroll
                    for (int j = 0; j < 4; ++j) acc[m][n][j] = 0.f;

#pragma unroll
            for (int lkt = 0; lkt < 8; ++lkt) {
                const int qq = lkt & 3;
                const int pa = (lkt < 4) ? qq : (4 + qq);
                const int pb = (lkt < 4) ? (4 + qq) : qq;
                uint4 Af[2];
#pragma unroll
                for (int m = 0; m < 2; ++m)
                    Af[m] = *(const uint4*)(sA + ((((rg * 2 + m) * 8 + pa) * 32) + lane) * 4);
#pragma unroll
                for (int n = 0; n < 2; ++n) {
                    uint2 Bf = *(const uint2*)(Bb + (((pb * 16 + cg * 2 + n) * 32) + lane) * 2);
#pragma unroll
                    for (int m = 0; m < 2; ++m) mma16816(acc[m][n], Af[m], Bf);
                }
            }
#pragma unroll
            for (int m = 0; m < 2; ++m)
#pragma unroll
                for (int n = 0; n < 2; ++n)
#pragma unroll
                    for (int j = 0; j < 4; ++j) acc[m][n][j] *= INV2048;
#pragma unroll
            for (int qq = 0; qq < 4; ++qq) {
                uint4 Af[2];
#pragma unroll
                for (int m = 0; m < 2; ++m)
                    Af[m] = *(const uint4*)(sA + ((((rg * 2 + m) * 8 + qq) * 32) + lane) * 4);
#pragma unroll
                for (int n = 0; n < 2; ++n) {
                    uint2 Bf = *(const uint2*)(Bb + (((qq * 16 + cg * 2 + n) * 32) + lane) * 2);
#pragma unroll
                    for (int m = 0; m < 2; ++m) mma16816(acc[m][n], Af[m], Bf);
                }
            }
            __syncthreads();

            if (ch + 2 < 4) {
                const char* src = (const char*)g_Bp + (size_t)(c0ch + ch + 2) * CHB;
                const uint32_t dst = sBaddr + (ch & 1) * CHB;
                for (int k = tid; k < CHB / 16; k += 512) cp16(dst + k * 16, src + k * 16);
                cp_commit();
            }

            const int cb = (c0ch + ch) * 128 + cg * 16 + 2 * (lane & 3);
#pragma unroll
            for (int n = 0; n < 2; ++n) {
                const int c0 = cb + n * 8;
                const float ea = sE2[c0], eb = sE2[c0 + 1];
#pragma unroll
                for (int m = 0; m < 2; ++m) {
                    const int ha = 2 * m, hb = 2 * m + 1;
                    float s0 = fmaf(-2.f, acc[m][n][0], ea);
                    float s1 = fmaf(-2.f, acc[m][n][1], eb);
                    float s2 = fmaf(-2.f, acc[m][n][2], ea);
                    float s3 = fmaf(-2.f, acc[m][n][3], eb);
                    if (s0 < best[ha]) { best[ha] = s0; bidx[ha] = c0; }
                    if (s1 < best[ha]) { best[ha] = s1; bidx[ha] = c0 + 1; }
                    if (s2 < best[hb]) { best[hb] = s2; bidx[hb] = c0; }
                    if (s3 < best[hb]) { best[hb] = s3; bidx[hb] = c0 + 1; }
                }
            }
        }

#pragma unroll
        for (int h = 0; h < 4; ++h) {
#pragma unroll
            for (int off = 1; off < 4; off <<= 1) {
                float os = __shfl_xor_sync(0xffffffffu, best[h], off);
                int   oi = __shfl_xor_sync(0xffffffffu, bidx[h], off);
                if (os < best[h] || (os == best[h] && oi < bidx[h])) { best[h] = os; bidx[h] = oi; }
            }
        }
        if ((lane & 3) == 0) {
            const int q = lane >> 2;
#pragma unroll
            for (int h = 0; h < 4; ++h) {
                const int m = h >> 1, hb = h & 1;
                const int row = rg * 32 + m * 16 + hb * 8 + q;
                sRF[row * 8 + cg] = best[h];
                sRI[row * 8 + cg] = bidx[h];
            }
        }
        __syncthreads();
        if (tid < ROWS_CTA && sL[tid] >= 0) {
            float bv = sRF[tid * 8];
            int   bi = sRI[tid * 8];
#pragma unroll
            for (int g = 1; g < 8; ++g) {
                float v = sRF[tid * 8 + g];
                int   i = sRI[tid * 8 + g];
                if (v < bv || (v == bv && i < bi)) { bv = v; bi = i; }
            }
            const unsigned long long key =
                ((unsigned long long)okey(bv) << 10) | (unsigned long long)bi;
            atomicMin(&g_slot[sL[tid]], key);
        }
        __syncthreads();
    }
}

// ---------------- flagged gather + fused finalize ----------------
// 148 blocks x 256 threads = 32 rows x 8 octants per iteration
__global__ void __launch_bounds__(256)
flag_fin_kernel(const float* __restrict__ x, const float* __restrict__ embed,
                float* __restrict__ out) {
    __shared__ float wsum[8];
    __shared__ int s_last;
    const int tid = threadIdx.x, lane = tid & 31, w = tid >> 5;
    const int rl = tid & 31, go = tid >> 5;    // 32 rows x 8 octants
    const int cnt = g_cnt;

    float my_sumsq = 0.f;
    for (int base = blockIdx.x * 32; base < cnt; base += gridDim.x * 32) {
        const int i = base + rl;
        if (i < cnt) {
            const int row = g_list[i];
            const int bi = (int)(g_slot[row] & 1023ull);
            if (go == 0) {
                out[IDX_OFF + row] = (float)bi;
                atomicAdd(&g_counts[bi], 1);
            }
            const int b_i = row >> 11, t_i = row & (TT - 1);
            const float4* ep = (const float4*)(embed + (size_t)bi * DIM + go * 8);
            const float* xp = x + ((size_t)b_i * DIM + go * 8) * TT + t_i;
            float* op = out + ((size_t)b_i * DIM + go * 8) * TT + t_i;
            float4 e0 = ep[0], e1 = ep[1];
            float ev[8] = {e0.x, e0.y, e0.z, e0.w, e1.x, e1.y, e1.z, e1.w};
            float xr[8];
#pragma unroll
            for (int j = 0; j < 8; ++j) xr[j] = xp[(size_t)j * TT];
#pragma unroll
            for (int j = 0; j < 8; ++j) {
                float d = ev[j] - xr[j];
                op[(size_t)j * TT] = xr[j] + d;
                my_sumsq = fmaf(d, d, my_sumsq);
            }
        }
    }
#pragma unroll
    for (int off = 16; off; off >>= 1)
        my_sumsq += __shfl_down_sync(0xffffffffu, my_sumsq, off);
    if (lane == 0) wsum[w] = my_sumsq;
    __syncthreads();
    if (w == 0) {
        float v = (lane < 8) ? wsum[lane] : 0.f;
#pragma unroll
        for (int off = 4; off; off >>= 1) v += __shfl_down_sync(0xffffffffu, v, off);
        if (lane == 0 && v != 0.f) atomicAdd(&g_sumsq, v);
        if (lane == 0 && v == 0.f) atomicAdd(&g_sumsq, 0.f);  // uniform participation
    }

    if (tid == 0) {
        __threadfence();
        s_last = (atomicAdd(&g_gdone, 1) == (int)gridDim.x - 1);
    }
    __syncthreads();
    if (!s_last) return;
    __threadfence();

    {
        __shared__ float f1[8], f2[8];
        float t1 = 0.f, t2 = 0.f;
        for (int c = tid; c < NUM_E; c += 256) {
            float p = (float)g_counts[c] * (1.0f / (float)NROWS);
            out[AVG_OFF + c] = p;
            t1 += p * logf(p + 1e-10f);
            t2 += p * logf(p * (float)NUM_E + 1e-10f);
        }
#pragma unroll
        for (int off = 16; off; off >>= 1) {
            t1 += __shfl_down_sync(0xffffffffu, t1, off);
            t2 += __shfl_down_sync(0xffffffffu, t2, off);
        }
        if (lane == 0) { f1[w] = t1; f2[w] = t2; }
        __syncthreads();
        if (w == 0) {
            float a = (lane < 8) ? f1[lane] : 0.f;
            float b = (lane < 8) ? f2[lane] : 0.f;
#pragma unroll
            for (int off = 4; off; off >>= 1) {
                a += __shfl_down_sync(0xffffffffu, a, off);
                b += __shfl_down_sync(0xffffffffu, b, off);
            }
            if (lane == 0) {
                out[PERP_OFF]   = expf(-a);
                out[USAGE_OFF]  = b;
                out[COMMIT_OFF] = 0.25f * g_sumsq / (float)NELEM;
            }
        }
    }
}

extern "C" void kernel_launch(void* const* d_in, const int* in_sizes, int n_in,
                              void* d_out, int out_size) {
    const float* x     = (const float*)d_in[0];
    const float* embed = (const float*)d_in[1];
    float* out = (float*)d_out;

    cudaFuncSetAttribute(vq_mma_kernel, cudaFuncAttributeMaxDynamicSharedMemorySize, SMEM_MAIN);
    cudaFuncSetAttribute(pass2_kernel, cudaFuncAttributeMaxDynamicSharedMemorySize, SMEM_P2);

    prep_kernel<<<32, 128>>>(embed);
    vq_mma_kernel<<<148, 512, SMEM_MAIN>>>(x, embed, out);
    pass2_kernel<<<296, 512, SMEM_P2>>>(x);
    flag_fin_kernel<<<148, 256>>>(x, embed, out);
}

// round 16
// speedup vs baseline: 1.0574x; 1.0574x over previous
#include <cuda_runtime.h>
#include <cuda_fp16.h>
#include <cstdint>
#include <math.h>

// ---------------- problem constants ----------------
#define NUM_E 1024
#define DIM   64
#define TT    2048
#define BB    32
#define NROWS (BB * TT)          // 65536
#define NELEM (BB * DIM * TT)    // 4194304

// output layout (flattened tuple, fp32)
#define COMMIT_OFF 4194304
#define PERP_OFF   4194305
#define AVG_OFF    4194306
#define IDX_OFF    4195330
#define USAGE_OFF  4260866

// ---------------- tiling ----------------
#define ROWS_CTA 64                  // rows per tile (4 m-tiles)
#define NTILES   (NROWS / ROWS_CTA)  // 1024
#define NCH      8                   // code chunks of 128
#define CHB      32768               // full 2-split packed chunk (8 pkt)
#define CHB2     16384               // split0 half (4 pkt)
#define INV2048  4.8828125e-4f

// ---- main kernel smem ----
#define SA_OFF   0                   // A frags split0: 8KB
#define SB_OFF   8192                // B split0 frags: 128KB
#define SE2_OFF  139264              // 4KB
#define SXN_OFF  143360              // x2 per row (64*4)
#define SRN_OFF  143616              // xi2 per row
#define SB1_OFF  143872
#define SI1_OFF  145920
#define SB2_OFF  147968
#define SX2_OFF  150016              // 64*4 (duplicate of sXn kept for clarity)
#define SMEM_MAIN 150528

// ---- pass2 kernel smem (R12-proven) ----
#define P2_SA    0                   // A frags 2-split: 16KB
#define P2_SB    16384               // 2 * 32KB
#define P2_SE2   81920               // 4KB
#define P2_SRF   86016               // 64*8*4
#define P2_SRI   88064               // 64*8*4
#define P2_SL    90112               // 64*4
#define SMEM_P2  90368

// ---------------- device scratch ----------------
__device__ __align__(16) unsigned char g_Bp[NCH * CHB];  // 2-split packed B
__device__ float g_e2[NUM_E];
__device__ float g_hm2[32];
__device__ float g_e0m2[32];
__device__ int   g_idx[NROWS];                 // -1 = flagged
__device__ unsigned long long g_slot[NROWS];   // packed (okey(score)<<10|idx); init for flagged rows
__device__ float g_x2[NROWS];                  // ||x||^2 for flagged rows
__device__ int   g_list[NROWS];
__device__ int   g_cnt;
__device__ int   g_gdone;
__device__ int   g_counts[NUM_E];
__device__ float g_sumsq;

// ---------------- helpers ----------------
__device__ __forceinline__ uint32_t smem_u32(const void* p) {
    uint32_t a;
    asm("{ .reg .u64 t; cvta.to.shared.u64 t, %1; cvt.u32.u64 %0, t; }" : "=r"(a) : "l"(p));
    return a;
}
__device__ __forceinline__ void cp16(uint32_t saddr, const void* g) {
    asm volatile("cp.async.cg.shared.global [%0], [%1], 16;" :: "r"(saddr), "l"(g));
}
__device__ __forceinline__ void cp_commit() {
    asm volatile("cp.async.commit_group;" ::: "memory");
}
__device__ __forceinline__ void mma16816(float* d, const uint4 a, const uint2 b) {
    asm volatile(
        "mma.sync.aligned.m16n8k16.row.col.f32.f16.f16.f32 "
        "{%0,%1,%2,%3}, {%4,%5,%6,%7}, {%8,%9}, {%0,%1,%2,%3};"
        : "+f"(d[0]), "+f"(d[1]), "+f"(d[2]), "+f"(d[3])
        : "r"(a.x), "r"(a.y), "r"(a.z), "r"(a.w), "r"(b.x), "r"(b.y));
}
__device__ __forceinline__ void split2(float v, uint32_t& u0, uint32_t& u1) {
    __half h0 = __float2half_rn(v);
    float f0 = __half2float(h0);
    __half h1 = __float2half_rn((v - f0) * 2048.0f);
    u0 = (uint32_t)__half_as_ushort(h0);
    u1 = (uint32_t)__half_as_ushort(h1);
}
__device__ __forceinline__ uint32_t okey(float f) {
    uint32_t b = __float_as_uint(f);
    return (b & 0x80000000u) ? ~b : (b | 0x80000000u);
}
__device__ __forceinline__ float okey_dec(uint32_t k) {
    return __uint_as_float((k & 0x80000000u) ? (k & 0x7FFFFFFFu) : ~k);
}

// ---------------- prep: 4 threads/code (32 blocks x 128 thr) ----------------
__global__ void prep_kernel(const float* __restrict__ embed) {
    __shared__ float smx1[4], smx2[4];
    const int tid = threadIdx.x, lane = tid & 31, w = tid >> 5;
    const int c = blockIdx.x * 32 + (tid >> 2);
    const int q = tid & 3;

    const float* e = embed + (size_t)c * DIM + q * 16;
    uint32_t h0[8], h1[8];
    float e2 = 0.f, e02 = 0.f, res2 = 0.f;
#pragma unroll
    for (int j = 0; j < 8; ++j) {
        float2 v = *(const float2*)(e + 2 * j);
        e2 += v.x * v.x + v.y * v.y;
        uint32_t a0, a1, b0, b1;
        split2(v.x, a0, a1);
        split2(v.y, b0, b1);
        float fa = __half2float(__ushort_as_half((unsigned short)a0));
        float fb = __half2float(__ushort_as_half((unsigned short)b0));
        e02 += fa * fa + fb * fb;
        float rx = v.x - fa, ry = v.y - fb;
        res2 += rx * rx + ry * ry;
        h0[j] = a0 | (b0 << 16);
        h1[j] = a1 | (b1 << 16);
    }
    e2 += __shfl_xor_sync(0xffffffffu, e2, 1);
    e2 += __shfl_xor_sync(0xffffffffu, e2, 2);
    if (q == 0) {
        g_e2[c] = e2;
        g_counts[c] = 0;
        if (c == 0) { g_sumsq = 0.f; g_cnt = 0; g_gdone = 0; }
    }

    const int chunk = c >> 7, n_in = c & 127, nt = n_in >> 3, lq = n_in & 7;
    uint32_t* dstb = (uint32_t*)(g_Bp + (size_t)chunk * CHB);
#pragma unroll
    for (int sp = 0; sp < 2; ++sp) {
        const int pkt = sp * 4 + q;
        const uint32_t* hp = sp ? h1 : h0;
#pragma unroll
        for (int cc = 0; cc < 4; ++cc) {
            uint32_t* d = dstb + (((pkt * 16 + nt) * 32) + 4 * lq + cc) * 2;
            d[0] = hp[cc];
            d[1] = hp[4 + cc];
        }
    }
#pragma unroll
    for (int o = 16; o; o >>= 1) {
        res2 = fmaxf(res2, __shfl_xor_sync(0xffffffffu, res2, o));
        e02  = fmaxf(e02,  __shfl_xor_sync(0xffffffffu, e02,  o));
    }
    if (lane == 0) { smx1[w] = res2; smx2[w] = e02; }
    __syncthreads();
    if (tid == 0) {
        g_hm2[blockIdx.x]  = fmaxf(fmaxf(smx1[0], smx1[1]), fmaxf(smx1[2], smx1[3]));
        g_e0m2[blockIdx.x] = fmaxf(fmaxf(smx2[0], smx2[1]), fmaxf(smx2[2], smx2[3]));
    }
}

// ---------------- main: persistent 1-product HMMA + top-2 + sound flag + commit-from-scores ----------------
__global__ void __launch_bounds__(512, 1)
vq_mma_kernel(const float* __restrict__ x) {
    extern __shared__ char sm[];
    uint32_t* sA  = (uint32_t*)(sm + SA_OFF);
    float*    sE2 = (float*)(sm + SE2_OFF);
    float*    sXn = (float*)(sm + SXN_OFF);   // stores x2
    float*    sRn = (float*)(sm + SRN_OFF);   // stores xi2
    float*    sB1 = (float*)(sm + SB1_OFF);
    int*      sI1 = (int*)(sm + SI1_OFF);
    float*    sB2 = (float*)(sm + SB2_OFF);
    const uint32_t sBaddr = smem_u32(sm + SB_OFF);

    const int tid = threadIdx.x, lane = tid & 31, w = tid >> 5;
    const int rg = w >> 3, cg = w & 7;

    // load split0 halves of all 8 chunks (128KB) ONCE
    for (int k = tid; k < 8192; k += 512) {
        const int chk = k >> 10, off = k & 1023;
        cp16(sBaddr + k * 16, (const char*)g_Bp + (size_t)chk * CHB + off * 16);
    }
    cp_commit();
    for (int i = tid; i < NUM_E; i += 512) sE2[i] = g_e2[i];

    float hm2 = g_hm2[0], e0m2 = g_e0m2[0];
#pragma unroll
    for (int i = 1; i < 32; ++i) {
        hm2 = fmaxf(hm2, g_hm2[i]);
        e0m2 = fmaxf(e0m2, g_e0m2[i]);
    }
    const float HM = sqrtf(hm2), E0M = sqrtf(e0m2);

    const int r = tid >> 3, o = tid & 7;
    const int q = o >> 1, halfq = o & 1;
    const int mt = r >> 4, rr = r & 15;
    const int wsel = ((rr < 8) ? 0 : 1) + (halfq ? 2 : 0);

    float xv[8];
    {
        const int grow = blockIdx.x * ROWS_CTA + r;
        const float* xp = x + (size_t)(grow >> 11) * (DIM * TT) + (grow & (TT - 1));
#pragma unroll
        for (int j = 0; j < 8; ++j) xv[j] = xp[(size_t)(8 * o + j) * TT];
    }
    asm volatile("cp.async.wait_group 0;" ::: "memory");
    __syncthreads();

    float commit_acc = 0.f;

    for (int tile = blockIdx.x; tile < NTILES; tile += gridDim.x) {
        {
            uint32_t h0[4];
            float x2 = 0.f, xi2 = 0.f;
#pragma unroll
            for (int j = 0; j < 4; ++j) {
                float va = xv[2 * j], vb = xv[2 * j + 1];
                __half ha = __float2half_rn(va), hb = __float2half_rn(vb);
                float fa = __half2float(ha), fb = __half2float(hb);
                float ra = va - fa, rb = vb - fb;
                x2 += va * va + vb * vb;
                xi2 += ra * ra + rb * rb;
                h0[j] = (uint32_t)__half_as_ushort(ha) | ((uint32_t)__half_as_ushort(hb) << 16);
            }
#pragma unroll
            for (int off = 1; off < 8; off <<= 1) {
                x2  += __shfl_xor_sync(0xffffffffu, x2,  off);
                xi2 += __shfl_xor_sync(0xffffffffu, xi2, off);
            }
            if (o == 0) { sXn[r] = x2; sRn[r] = xi2; }
#pragma unroll
            for (int cc = 0; cc < 4; ++cc)
                sA[(((mt * 4 + q) * 32) + 4 * (rr & 7) + cc) * 4 + wsel] = h0[cc];
        }
        __syncthreads();

        float xn[8];
        {
            const int ntile = tile + gridDim.x;
            if (ntile < NTILES) {
                const int grow = ntile * ROWS_CTA + r;
                const float* xp = x + (size_t)(grow >> 11) * (DIM * TT) + (grow & (TT - 1));
#pragma unroll
                for (int j = 0; j < 8; ++j) xn[j] = xp[(size_t)(8 * o + j) * TT];
            } else {
#pragma unroll
                for (int j = 0; j < 8; ++j) xn[j] = 0.f;
            }
        }

        float b1_[4] = {3.4e38f, 3.4e38f, 3.4e38f, 3.4e38f};
        float b2_[4] = {3.4e38f, 3.4e38f, 3.4e38f, 3.4e38f};
        int   i1_[4] = {0, 0, 0, 0};

#define UPD(h, s, c) do { \
        if ((s) < b1_[h]) { b2_[h] = b1_[h]; b1_[h] = (s); i1_[h] = (c); } \
        else if ((s) < b2_[h]) b2_[h] = (s); \
    } while (0)

        for (int ch = 0; ch < NCH; ++ch) {
            const uint32_t* Bb = (const uint32_t*)(sm + SB_OFF + ch * CHB2);
            float acc[2][2][4];
#pragma unroll
            for (int m = 0; m < 2; ++m)
#pragma unroll
                for (int n = 0; n < 2; ++n)
#pragma unroll
                    for (int j = 0; j < 4; ++j) acc[m][n][j] = 0.f;
#pragma unroll
            for (int kt = 0; kt < 4; ++kt) {
                uint4 Af[2];
#pragma unroll
                for (int m = 0; m < 2; ++m)
                    Af[m] = *(const uint4*)(sA + ((((rg * 2 + m) * 4 + kt) * 32) + lane) * 4);
#pragma unroll
                for (int n = 0; n < 2; ++n) {
                    uint2 Bf = *(const uint2*)(Bb + (((kt * 16 + cg * 2 + n) * 32) + lane) * 2);
#pragma unroll
                    for (int m = 0; m < 2; ++m) mma16816(acc[m][n], Af[m], Bf);
                }
            }
            const int cb = ch * 128 + cg * 16 + 2 * (lane & 3);
#pragma unroll
            for (int n = 0; n < 2; ++n) {
                const int c0 = cb + n * 8;
                const float ea = sE2[c0], eb = sE2[c0 + 1];
#pragma unroll
                for (int m = 0; m < 2; ++m) {
                    const int ha = 2 * m, hb = 2 * m + 1;
                    float s0 = fmaf(-2.f, acc[m][n][0], ea);
                    float s1 = fmaf(-2.f, acc[m][n][1], eb);
                    float s2 = fmaf(-2.f, acc[m][n][2], ea);
                    float s3 = fmaf(-2.f, acc[m][n][3], eb);
                    UPD(ha, s0, c0); UPD(ha, s1, c0 + 1);
                    UPD(hb, s2, c0); UPD(hb, s3, c0 + 1);
                }
            }
        }
#undef UPD

#pragma unroll
        for (int h = 0; h < 4; ++h) {
#pragma unroll
            for (int off = 1; off < 4; off <<= 1) {
                float ob1 = __shfl_xor_sync(0xffffffffu, b1_[h], off);
                int   oi1 = __shfl_xor_sync(0xffffffffu, i1_[h], off);
                float ob2 = __shfl_xor_sync(0xffffffffu, b2_[h], off);
                if (ob1 < b1_[h] || (ob1 == b1_[h] && oi1 < i1_[h])) {
                    b2_[h] = fminf(b1_[h], ob2);
                    b1_[h] = ob1; i1_[h] = oi1;
                } else {
                    b2_[h] = fminf(b2_[h], ob1);
                }
            }
        }
        if ((lane & 3) == 0) {
            const int qq = lane >> 2;
#pragma unroll
            for (int h = 0; h < 4; ++h) {
                const int m = h >> 1, hb = h & 1;
                const int row = rg * 32 + m * 16 + hb * 8 + qq;
                sB1[row * 8 + cg] = b1_[h];
                sI1[row * 8 + cg] = i1_[h];
                sB2[row * 8 + cg] = b2_[h];
            }
        }
        __syncthreads();

        if (tid < ROWS_CTA) {
            float B1 = sB1[tid * 8], B2 = sB2[tid * 8];
            int   I1 = sI1[tid * 8];
#pragma unroll
            for (int g = 1; g < 8; ++g) {
                float ob1 = sB1[tid * 8 + g], ob2 = sB2[tid * 8 + g];
                int   oi1 = sI1[tid * 8 + g];
                if (ob1 < B1 || (ob1 == B1 && oi1 < I1)) {
                    B2 = fminf(B1, ob2);
                    B1 = ob1; I1 = oi1;
                } else {
                    B2 = fminf(B2, ob1);
                }
            }
            const float x2 = sXn[tid];
            const float Wt = 4.0f * (sqrtf(x2) * HM + sqrtf(sRn[tid]) * E0M) + 0.02f;
            const int grow = tile * ROWS_CTA + tid;
            if (B2 - B1 > Wt) {
                g_idx[grow] = I1;
                atomicAdd(&g_counts[I1], 1);
                commit_acc += B1 + x2;          // true dist ~ score + ||x||^2
            } else {
                g_idx[grow] = -1;
                g_slot[grow] = 0xFFFFFFFFFFFFFFFFull;
                g_x2[grow] = x2;
                const int pos = atomicAdd(&g_cnt, 1);
                g_list[pos] = grow;
            }
        }
        __syncthreads();

#pragma unroll
        for (int j = 0; j < 8; ++j) xv[j] = xn[j];
    }

    // CTA-level commitment reduction, one atomic per CTA
    {
        __shared__ float wsum[16];
#pragma unroll
        for (int off = 16; off; off >>= 1)
            commit_acc += __shfl_down_sync(0xffffffffu, commit_acc, off);
        if (lane == 0) wsum[w] = commit_acc;
        __syncthreads();
        if (w == 0) {
            float v = (lane < 16) ? wsum[lane] : 0.f;
#pragma unroll
            for (int off = 8; off; off >>= 1) v += __shfl_down_sync(0xffffffffu, v, off);
            if (lane == 0) atomicAdd(&g_sumsq, v);
        }
    }
}

// ---------------- pass2 (R12-proven): exact 2-split HMMA rescore, half-tiles ----------------
__global__ void __launch_bounds__(512, 2)
pass2_kernel(const float* __restrict__ x) {
    extern __shared__ char sm[];
    uint32_t* sA  = (uint32_t*)(sm + P2_SA);
    float*    sE2 = (float*)(sm + P2_SE2);
    float*    sRF = (float*)(sm + P2_SRF);
    int*      sRI = (int*)(sm + P2_SRI);
    int*      sL  = (int*)(sm + P2_SL);
    const uint32_t sBaddr = smem_u32(sm + P2_SB);

    const int tid = threadIdx.x, lane = tid & 31, w = tid >> 5;
    const int rg = w >> 3, cg = w & 7;
    const int cnt = g_cnt;

    for (int i = tid; i < NUM_E; i += 512) sE2[i] = g_e2[i];

    for (int ht = blockIdx.x; (ht >> 1) * 64 < cnt; ht += gridDim.x) {
        const int pair = ht >> 1, chalf = ht & 1;
        const int c0ch = chalf * 4;

        if (tid < ROWS_CTA) {
            const int p = pair * ROWS_CTA + tid;
            sL[tid] = (p < cnt) ? g_list[p] : -1;
        }
        __syncthreads();

        for (int k = tid; k < CHB / 16; k += 512)
            cp16(sBaddr + k * 16, (const char*)g_Bp + (size_t)c0ch * CHB + k * 16);
        cp_commit();
        for (int k = tid; k < CHB / 16; k += 512)
            cp16(sBaddr + CHB + k * 16, (const char*)g_Bp + (size_t)(c0ch + 1) * CHB + k * 16);
        cp_commit();

        {
            const int r = tid >> 3, o = tid & 7;
            const int q = o >> 1, halfq = o & 1;
            int grow = sL[r];
            if (grow < 0) grow = 0;
            const float* xp = x + (size_t)(grow >> 11) * (DIM * TT) + (grow & (TT - 1));
            uint32_t h0[4], h1[4];
#pragma unroll
            for (int j = 0; j < 4; ++j) {
                float va = xp[(size_t)(8 * o + 2 * j) * TT];
                float vb = xp[(size_t)(8 * o + 2 * j + 1) * TT];
                uint32_t a0, a1, b0, b1;
                split2(va, a0, a1);
                split2(vb, b0, b1);
                h0[j] = a0 | (b0 << 16);
                h1[j] = a1 | (b1 << 16);
            }
            const int mt = r >> 4, rr = r & 15;
            const int wsel = ((rr < 8) ? 0 : 1) + (halfq ? 2 : 0);
#pragma unroll
            for (int sp = 0; sp < 2; ++sp) {
                const int pkt = sp * 4 + q;
                const uint32_t* hp = sp ? h1 : h0;
#pragma unroll
                for (int cc = 0; cc < 4; ++cc)
                    sA[(((mt * 8 + pkt) * 32) + 4 * (rr & 7) + cc) * 4 + wsel] = hp[cc];
            }
        }
        __syncthreads();

        float best[4];
        int   bidx[4];
#pragma unroll
        for (int h = 0; h < 4; ++h) { best[h] = 3.4e38f; bidx[h] = 0; }

        for (int ch = 0; ch < 4; ++ch) {
            if (ch < 3) asm volatile("cp.async.wait_group 1;" ::: "memory");
            else        asm volatile("cp.async.wait_group 0;" ::: "memory");
            __syncthreads();
            const uint32_t* Bb = (const uint32_t*)(sm + P2_SB + (ch & 1) * CHB);

            float acc[2][2][4];
#pragma unroll
            for (int m = 0; m < 2; ++m)
#pragma unroll
                for (int n = 0; n < 2; ++n)
#pragma unroll
                    for (int j = 0; j < 4; ++j) acc[m][n][j] = 0.f;

#pragma unroll
            for (int lkt = 0; lkt < 8; ++lkt) {
                const int qq = lkt & 3;
                const int pa = (lkt < 4) ? qq : (4 + qq);
                const int pb = (lkt < 4) ? (4 + qq) : qq;
                uint4 Af[2];
#pragma unroll
                for (int m = 0; m < 2; ++m)
                    Af[m] = *(const uint4*)(sA + ((((rg * 2 + m) * 8 + pa) * 32) + lane) * 4);
#pragma unroll
                for (int n = 0; n < 2; ++n) {
                    uint2 Bf = *(const uint2*)(Bb + (((pb * 16 + cg * 2 + n) * 32) + lane) * 2);
#pragma unroll
                    for (int m = 0; m < 2; ++m) mma16816(acc[m][n], Af[m], Bf);
                }
            }
#pragma unroll
            for (int m = 0; m < 2; ++m)
#pragma unroll
                for (int n = 0; n < 2; ++n)
#pragma unroll
                    for (int j = 0; j < 4; ++j) acc[m][n][j] *= INV2048;
#pragma unroll
            for (int qq = 0; qq < 4; ++qq) {
                uint4 Af[2];
#pragma unroll
                for (int m = 0; m < 2; ++m)
                    Af[m] = *(const uint4*)(sA + ((((rg * 2 + m) * 8 + qq) * 32) + lane) * 4);
#pragma unroll
                for (int n = 0; n < 2; ++n) {
                    uint2 Bf = *(const uint2*)(Bb + (((qq * 16 + cg * 2 + n) * 32) + lane) * 2);
#pragma unroll
                    for (int m = 0; m < 2; ++m) mma16816(acc[m][n], Af[m], Bf);
                }
            }
            __syncthreads();

            if (ch + 2 < 4) {
                const char* src = (const char*)g_Bp + (size_t)(c0ch + ch + 2) * CHB;
                const uint32_t dst = sBaddr + (ch & 1) * CHB;
                for (int k = tid; k < CHB / 16; k += 512) cp16(dst + k * 16, src + k * 16);
                cp_commit();
            }

            const int cb = (c0ch + ch) * 128 + cg * 16 + 2 * (lane & 3);
#pragma unroll
            for (int n = 0; n < 2; ++n) {
                const int c0 = cb + n * 8;
                const float ea = sE2[c0], eb = sE2[c0 + 1];
#pragma unroll
                for (int m = 0; m < 2; ++m) {
                    const int ha = 2 * m, hb = 2 * m + 1;
                    float s0 = fmaf(-2.f, acc[m][n][0], ea);
                    float s1 = fmaf(-2.f, acc[m][n][1], eb);
                    float s2 = fmaf(-2.f, acc[m][n][2], ea);
                    float s3 = fmaf(-2.f, acc[m][n][3], eb);
                    if (s0 < best[ha]) { best[ha] = s0; bidx[ha] = c0; }
                    if (s1 < best[ha]) { best[ha] = s1; bidx[ha] = c0 + 1; }
                    if (s2 < best[hb]) { best[hb] = s2; bidx[hb] = c0; }
                    if (s3 < best[hb]) { best[hb] = s3; bidx[hb] = c0 + 1; }
                }
            }
        }

#pragma unroll
        for (int h = 0; h < 4; ++h) {
#pragma unroll
            for (int off = 1; off < 4; off <<= 1) {
                float os = __shfl_xor_sync(0xffffffffu, best[h], off);
                int   oi = __shfl_xor_sync(0xffffffffu, bidx[h], off);
                if (os < best[h] || (os == best[h] && oi < bidx[h])) { best[h] = os; bidx[h] = oi; }
            }
        }
        if ((lane & 3) == 0) {
            const int q = lane >> 2;
#pragma unroll
            for (int h = 0; h < 4; ++h) {
                const int m = h >> 1, hb = h & 1;
                const int row = rg * 32 + m * 16 + hb * 8 + q;
                sRF[row * 8 + cg] = best[h];
                sRI[row * 8 + cg] = bidx[h];
            }
        }
        __syncthreads();
        if (tid < ROWS_CTA && sL[tid] >= 0) {
            float bv = sRF[tid * 8];
            int   bi = sRI[tid * 8];
#pragma unroll
            for (int g = 1; g < 8; ++g) {
                float v = sRF[tid * 8 + g];
                int   i = sRI[tid * 8 + g];
                if (v < bv || (v == bv && i < bi)) { bv = v; bi = i; }
            }
            const unsigned long long key =
                ((unsigned long long)okey(bv) << 10) | (unsigned long long)bi;
            atomicMin(&g_slot[sL[tid]], key);
        }
        __syncthreads();
    }
}

// ---------------- gather: write quantized = embed[winner] + idx + flagged commit + finalize ----------------
// block 256 = 64 rows x 4 dim-quarters
__global__ void __launch_bounds__(256)
gather_fin_kernel(const float* __restrict__ embed, float* __restrict__ out) {
    __shared__ float wsum[8];
    __shared__ int s_last;
    const int tid = threadIdx.x, lane = tid & 31, w = tid >> 5;
    const int r = tid & 63, q = tid >> 6;
    const int row = blockIdx.x * 64 + r;
    const int b_i = row >> 11, t_i = row & (TT - 1);

    const int idx0 = g_idx[row];
    int bi = idx0;
    float cadd = 0.f;
    if (idx0 < 0) {
        const unsigned long long key = g_slot[row];
        bi = (int)(key & 1023ull);
        if (q == 0) {
            cadd = okey_dec((uint32_t)(key >> 10)) + g_x2[row];
            atomicAdd(&g_counts[bi], 1);
        }
    }
    if (q == 0) out[IDX_OFF + row] = (float)bi;

    // quantized_st == quantized (to ~1 ulp): write embed row directly, no x read
    const float4* ep = (const float4*)(embed + (size_t)bi * DIM + q * 16);
    float* op = out + ((size_t)b_i * DIM + q * 16) * TT + t_i;
    float4 e0 = ep[0], e1 = ep[1], e2 = ep[2], e3 = ep[3];
    float ev[16] = {e0.x, e0.y, e0.z, e0.w, e1.x, e1.y, e1.z, e1.w,
                    e2.x, e2.y, e2.z, e2.w, e3.x, e3.y, e3.z, e3.w};
#pragma unroll
    for (int j = 0; j < 16; ++j) op[(size_t)j * TT] = ev[j];

    // flagged commit contributions
#pragma unroll
    for (int off = 16; off; off >>= 1) cadd += __shfl_down_sync(0xffffffffu, cadd, off);
    if (lane == 0) wsum[w] = cadd;
    __syncthreads();
    if (w == 0) {
        float v = (lane < 8) ? wsum[lane] : 0.f;
#pragma unroll
        for (int off = 4; off; off >>= 1) v += __shfl_down_sync(0xffffffffu, v, off);
        if (lane == 0) atomicAdd(&g_sumsq, v);
    }

    if (tid == 0) {
        __threadfence();
        s_last = (atomicAdd(&g_gdone, 1) == (int)gridDim.x - 1);
    }
    __syncthreads();
    if (!s_last) return;
    __threadfence();

    {
        __shared__ float f1[8], f2[8];
        float t1 = 0.f, t2 = 0.f;
        for (int c = tid; c < NUM_E; c += 256) {
            float p = (float)g_counts[c] * (1.0f / (float)NROWS);
            out[AVG_OFF + c] = p;
            t1 += p * logf(p + 1e-10f);
            t2 += p * logf(p * (float)NUM_E + 1e-10f);
        }
#pragma unroll
        for (int off = 16; off; off >>= 1) {
            t1 += __shfl_down_sync(0xffffffffu, t1, off);
            t2 += __shfl_down_sync(0xffffffffu, t2, off);
        }
        if (lane == 0) { f1[w] = t1; f2[w] = t2; }
        __syncthreads();
        if (w == 0) {
            float a = (lane < 8) ? f1[lane] : 0.f;
            float b = (lane < 8) ? f2[lane] : 0.f;
#pragma unroll
            for (int off = 4; off; off >>= 1) {
                a += __shfl_down_sync(0xffffffffu, a, off);
                b += __shfl_down_sync(0xffffffffu, b, off);
            }
            if (lane == 0) {
                out[PERP_OFF]   = expf(-a);
                out[USAGE_OFF]  = b;
                out[COMMIT_OFF] = 0.25f * g_sumsq / (float)NELEM;
            }
        }
    }
}

extern "C" void kernel_launch(void* const* d_in, const int* in_sizes, int n_in,
                              void* d_out, int out_size) {
    const float* x     = (const float*)d_in[0];
    const float* embed = (const float*)d_in[1];
    float* out = (float*)d_out;

    cudaFuncSetAttribute(vq_mma_kernel, cudaFuncAttributeMaxDynamicSharedMemorySize, SMEM_MAIN);
    cudaFuncSetAttribute(pass2_kernel, cudaFuncAttributeMaxDynamicSharedMemorySize, SMEM_P2);

    prep_kernel<<<32, 128>>>(embed);
    vq_mma_kernel<<<148, 512, SMEM_MAIN>>>(x);
    pass2_kernel<<<296, 512, SMEM_P2>>>(x);
    gather_fin_kernel<<<NROWS / 64, 256>>>(embed, out);
}